// round 1
// baseline (speedup 1.0000x reference)
#include <cuda_runtime.h>

#define NLAYERS 2
#define NB 4
#define BS 256
#define NHID 1024
#define NINP 1024
#define NTOK 32000
#define T 64
#define B 64
#define DK 16

// ---------------- scratch (device globals: no allocation allowed) ----------
__device__ float g_xbuf[2][(size_t)T * B * NHID];  // ping-pong layer activations
__device__ float g_h[B * NHID];                    // current h state
__device__ float g_c[B * NHID];                    // current c state
__device__ float g_hl[B * NHID];                   // h_lstm (pre-MHA)

// ---------------- f32x2 helpers (sm_103a packed fp32 FMA) ------------------
__device__ __forceinline__ unsigned long long splat2(float a) {
    unsigned long long r;
    unsigned int u = __float_as_uint(a);
    asm("mov.b64 %0, {%1, %1};" : "=l"(r) : "r"(u));
    return r;
}
__device__ __forceinline__ void ffma2(unsigned long long &c, unsigned long long a,
                                      unsigned long long b) {
    asm("fma.rn.f32x2 %0, %1, %2, %0;" : "+l"(c) : "l"(a), "l"(b));
}
__device__ __forceinline__ float2 unpk(unsigned long long v) {
    unsigned int x, y;
    asm("mov.b64 {%0, %1}, %2;" : "=r"(x), "=r"(y) : "l"(v));
    return make_float2(__uint_as_float(x), __uint_as_float(y));
}
__device__ __forceinline__ float sigmoidf_(float x) { return 1.f / (1.f + expf(-x)); }

// ---------------- embedding gather ------------------------------------------
__global__ void k_embed(const int* __restrict__ tokens, const float* __restrict__ embW,
                        float* __restrict__ x) {
    int tb = blockIdx.x;  // t*B+b
    int tok = tokens[tb];
    const float4* src = (const float4*)(embW + (size_t)tok * NINP);
    float4* dst = (float4*)(x + (size_t)tb * NINP);
    dst[threadIdx.x] = src[threadIdx.x];  // 256 threads * 4 = 1024 floats
}

// ---------------- 64K-float copy (state init / writeout) --------------------
__global__ void k_copy4(const float4* __restrict__ s, float4* __restrict__ d) {
    int i = blockIdx.x * blockDim.x + threadIdx.x;
    d[i] = s[i];
}

// ---------------- gates GEMM + LSTM cell (one layer, one timestep) ----------
// grid: (BS/8=32, NB=4) = 128 CTAs, 128 threads.
// CTA computes gates for all 64 batches x 8 j-values x 4 gates of block n,
// then fuses the LSTM cell update in the epilogue.
__global__ void __launch_bounds__(128) k_gates(
    const float* __restrict__ xt,   // [B][NINP]
    const float* __restrict__ Wih,  // [NB][4BS][NINP] (layer slice)
    const float* __restrict__ Whh,  // [NB][4BS][BS]
    const float* __restrict__ bih, const float* __restrict__ bhh,  // [NB][4BS]
    const float* __restrict__ hprev,                               // [B][NHID]
    float* __restrict__ c, float* __restrict__ hl) {
    __shared__ __align__(16) float sa[32][65];  // [k][b], stride 65 -> conflict-free
    __shared__ __align__(16) float sw[32][34];  // [k][jj*4+g], stride 34 (8B aligned)
    const int n = blockIdx.y;
    const int j0 = blockIdx.x * 8;
    const int tid = threadIdx.x;
    const int tj = tid & 7, tb4 = tid >> 3;  // tj: j within tile, tb4: b-group 0..15

    unsigned long long acc[4][2];
#pragma unroll
    for (int i = 0; i < 4; i++) { acc[i][0] = 0ULL; acc[i][1] = 0ULL; }

#pragma unroll
    for (int phase = 0; phase < 2; ++phase) {
        const float* A = phase ? (hprev + n * BS) : xt;
        const int lda = phase ? NHID : NINP;
        const int K = phase ? BS : NINP;
        const float* W = phase ? (Whh + n * 4 * BS * BS) : (Wih + (size_t)n * 4 * BS * NINP);
        const int ldw = phase ? BS : NINP;
        for (int k0 = 0; k0 < K; k0 += 32) {
            __syncthreads();
            // A tile: 64 b-rows x 32 k, transposed into smem
#pragma unroll
            for (int i = 0; i < 4; ++i) {
                int lid = tid + i * 128;
                int bb = lid >> 3, kq = lid & 7;
                float4 v = *(const float4*)(A + (size_t)bb * lda + k0 + kq * 4);
                sa[kq * 4 + 0][bb] = v.x; sa[kq * 4 + 1][bb] = v.y;
                sa[kq * 4 + 2][bb] = v.z; sa[kq * 4 + 3][bb] = v.w;
            }
            // W tile: 32 cols (8 j x 4 gates) x 32 k, transposed
#pragma unroll
            for (int i = 0; i < 2; ++i) {
                int lid = tid + i * 128;
                int col = lid >> 3, kq = lid & 7;
                int jj = col >> 2, g = col & 3;
                float4 v = *(const float4*)(W + (size_t)(g * BS + j0 + jj) * ldw + k0 + kq * 4);
                sw[kq * 4 + 0][col] = v.x; sw[kq * 4 + 1][col] = v.y;
                sw[kq * 4 + 2][col] = v.z; sw[kq * 4 + 3][col] = v.w;
            }
            __syncthreads();
#pragma unroll
            for (int k = 0; k < 32; ++k) {
                unsigned long long w01 = *(const unsigned long long*)&sw[k][tj * 4];
                unsigned long long w23 = *(const unsigned long long*)&sw[k][tj * 4 + 2];
#pragma unroll
                for (int bi = 0; bi < 4; ++bi) {
                    unsigned long long as = splat2(sa[k][tb4 * 4 + bi]);
                    ffma2(acc[bi][0], as, w01);
                    ffma2(acc[bi][1], as, w23);
                }
            }
        }
    }
    // epilogue: biases + LSTM cell
    const int j = j0 + tj;
    const float b_i = bih[n * 4 * BS + 0 * BS + j] + bhh[n * 4 * BS + 0 * BS + j];
    const float b_f = bih[n * 4 * BS + 1 * BS + j] + bhh[n * 4 * BS + 1 * BS + j];
    const float b_g = bih[n * 4 * BS + 2 * BS + j] + bhh[n * 4 * BS + 2 * BS + j];
    const float b_o = bih[n * 4 * BS + 3 * BS + j] + bhh[n * 4 * BS + 3 * BS + j];
#pragma unroll
    for (int bi = 0; bi < 4; ++bi) {
        int bb = tb4 * 4 + bi;
        float2 g01 = unpk(acc[bi][0]);
        float2 g23 = unpk(acc[bi][1]);
        float gi = g01.x + b_i, gf = g01.y + b_f;
        float gg = g23.x + b_g, go = g23.y + b_o;
        int idx = bb * NHID + n * BS + j;
        float cn = sigmoidf_(gf) * c[idx] + sigmoidf_(gi) * tanhf(gg);
        c[idx] = cn;
        hl[idx] = sigmoidf_(go) * tanhf(cn);
    }
}

// ---------------- fused MHA + residual + LayerNorm ---------------------------
// grid: (NB=4, B=64) = 256 CTAs, 256 threads. k/v recomputed per CTA (tiny).
__global__ void __launch_bounds__(256) k_mha(
    const float* __restrict__ hl, float* __restrict__ h,
    const float* __restrict__ wq, const float* __restrict__ bq,
    const float* __restrict__ wk, const float* __restrict__ bk,
    const float* __restrict__ wv, const float* __restrict__ bv,
    const float* __restrict__ wfc, const float* __restrict__ bfc,
    const float* __restrict__ lng, const float* __restrict__ lnb,
    float* __restrict__ ys) {
    const int n = blockIdx.x, b = blockIdx.y;
    __shared__ float sh[NB][BS];
    __shared__ float sq[DK], sk[NB][DK], sv[NB][DK], ssc[NB], sp[NB], so[DK];
    __shared__ float sred[8];
    const int tid = threadIdx.x;
#pragma unroll
    for (int i = 0; i < 4; ++i) {
        int idx = tid + i * 256;
        sh[idx >> 8][idx & 255] = hl[b * NHID + idx];
    }
    __syncthreads();
    if (tid < 144) {  // q(16) + k(64) + v(64) projections
        const float *wp, *bp, *hv; float* dst; int d;
        if (tid < 16) { d = tid; wp = wq; bp = bq; hv = sh[n]; dst = &sq[d]; }
        else if (tid < 80) { int m = (tid - 16) >> 4; d = (tid - 16) & 15;
                             wp = wk; bp = bk; hv = sh[m]; dst = &sk[m][d]; }
        else { int m = (tid - 80) >> 4; d = (tid - 80) & 15;
               wp = wv; bp = bv; hv = sh[m]; dst = &sv[m][d]; }
        const float* w = wp + d * BS;
        float a0 = 0, a1 = 0, a2 = 0, a3 = 0;
#pragma unroll 8
        for (int jj = 0; jj < BS; jj += 4) {
            a0 += hv[jj] * w[jj];         a1 += hv[jj + 1] * w[jj + 1];
            a2 += hv[jj + 2] * w[jj + 2]; a3 += hv[jj + 3] * w[jj + 3];
        }
        *dst = a0 + a1 + a2 + a3 + bp[d];
    }
    __syncthreads();
    if (tid < 4) {
        float s = 0;
#pragma unroll
        for (int d = 0; d < DK; ++d) s += sq[d] * sk[tid][d];
        ssc[tid] = s * 0.25f;  // 1/sqrt(DK)
    }
    __syncthreads();
    if (tid < 4) {
        float mx = fmaxf(fmaxf(ssc[0], ssc[1]), fmaxf(ssc[2], ssc[3]));
        float sum = expf(ssc[0] - mx) + expf(ssc[1] - mx) +
                    expf(ssc[2] - mx) + expf(ssc[3] - mx);
        sp[tid] = expf(ssc[tid] - mx) / sum;
    }
    __syncthreads();
    if (tid < DK) {
        float o = 0;
#pragma unroll
        for (int m = 0; m < NB; ++m) o += sp[m] * sv[m][tid];
        so[tid] = o;
    }
    __syncthreads();
    float val = bfc[tid] + sh[n][tid];  // fc + residual
#pragma unroll
    for (int d = 0; d < DK; ++d) val += so[d] * wfc[tid * DK + d];
    // LayerNorm over 256
    float s = val;
#pragma unroll
    for (int off = 16; off; off >>= 1) s += __shfl_down_sync(0xffffffffu, s, off);
    if ((tid & 31) == 0) sred[tid >> 5] = s;
    __syncthreads();
    float mu = 0;
#pragma unroll
    for (int i = 0; i < 8; ++i) mu += sred[i];
    mu *= (1.f / BS);
    __syncthreads();
    float dv = val - mu;
    float s2 = dv * dv;
#pragma unroll
    for (int off = 16; off; off >>= 1) s2 += __shfl_down_sync(0xffffffffu, s2, off);
    if ((tid & 31) == 0) sred[tid >> 5] = s2;
    __syncthreads();
    float var = 0;
#pragma unroll
    for (int i = 0; i < 8; ++i) var += sred[i];
    var *= (1.f / BS);
    float y = dv * rsqrtf(var + 1e-5f) * lng[tid] + lnb[tid];
    int idx = b * NHID + n * BS + tid;
    h[idx] = y;
    ys[idx] = y;
}

// ---------------- decoder GEMM: [4096,1024] x [32000,1024]^T + bias ----------
// 128x128 CTA tile, 8x8 thread tile in f32x2, register-prefetch double buffer.
__global__ void __launch_bounds__(256, 2) k_dec(
    const float* __restrict__ X, const float* __restrict__ Wd,
    const float* __restrict__ bias, float* __restrict__ out) {
    __shared__ __align__(16) float sa[16][132];
    __shared__ __align__(16) float sb[16][132];
    const int m0 = blockIdx.x * 128;
    const int n0 = blockIdx.y * 128;
    const int tid = threadIdx.x;
    const int tn = tid & 15, tm = tid >> 4;
    unsigned long long acc[8][4];
#pragma unroll
    for (int i = 0; i < 8; i++)
#pragma unroll
        for (int p = 0; p < 4; p++) acc[i][p] = 0ULL;

    float4 pa[2], pb[2];
#pragma unroll
    for (int i = 0; i < 2; ++i) {
        int lid = tid + i * 256;
        int row = lid >> 2, kq = lid & 3;
        pa[i] = *(const float4*)(X + (size_t)(m0 + row) * NHID + kq * 4);
        pb[i] = *(const float4*)(Wd + (size_t)(n0 + row) * NHID + kq * 4);
    }
    for (int k0 = 0; k0 < NHID; k0 += 16) {
#pragma unroll
        for (int i = 0; i < 2; ++i) {
            int lid = tid + i * 256;
            int row = lid >> 2, kq = lid & 3;
            sa[kq * 4 + 0][row] = pa[i].x; sa[kq * 4 + 1][row] = pa[i].y;
            sa[kq * 4 + 2][row] = pa[i].z; sa[kq * 4 + 3][row] = pa[i].w;
            sb[kq * 4 + 0][row] = pb[i].x; sb[kq * 4 + 1][row] = pb[i].y;
            sb[kq * 4 + 2][row] = pb[i].z; sb[kq * 4 + 3][row] = pb[i].w;
        }
        __syncthreads();
        if (k0 + 16 < NHID) {
#pragma unroll
            for (int i = 0; i < 2; ++i) {
                int lid = tid + i * 256;
                int row = lid >> 2, kq = lid & 3;
                pa[i] = *(const float4*)(X + (size_t)(m0 + row) * NHID + (k0 + 16) + kq * 4);
                pb[i] = *(const float4*)(Wd + (size_t)(n0 + row) * NHID + (k0 + 16) + kq * 4);
            }
        }
#pragma unroll
        for (int k = 0; k < 16; ++k) {
            unsigned long long b2[4];
#pragma unroll
            for (int p = 0; p < 4; ++p)
                b2[p] = *(const unsigned long long*)&sb[k][p * 32 + tn * 2];
#pragma unroll
            for (int i = 0; i < 8; ++i) {
                unsigned long long as = splat2(sa[k][tm * 8 + i]);
#pragma unroll
                for (int p = 0; p < 4; ++p) ffma2(acc[i][p], as, b2[p]);
            }
        }
        __syncthreads();
    }
#pragma unroll
    for (int i = 0; i < 8; ++i) {
        int m = m0 + tm * 8 + i;
#pragma unroll
        for (int p = 0; p < 4; ++p) {
            int nn = n0 + p * 32 + tn * 2;
            float2 v = unpk(acc[i][p]);
            float2 r = make_float2(v.x + bias[nn], v.y + bias[nn + 1]);
            *(float2*)(out + (size_t)m * NTOK + nn) = r;
        }
    }
}

// ---------------- host driver ------------------------------------------------
extern "C" void kernel_launch(void* const* d_in, const int* in_sizes, int n_in,
                              void* d_out, int out_size) {
    const int* tokens = (const int*)d_in[0];
    const float* h0 = (const float*)d_in[1];
    const float* c0 = (const float*)d_in[2];
    const float* embW = (const float*)d_in[3];
    const float* Wih = (const float*)d_in[4];
    const float* Whh = (const float*)d_in[5];
    const float* bih = (const float*)d_in[6];
    const float* bhh = (const float*)d_in[7];
    const float* wq = (const float*)d_in[8];
    const float* bq = (const float*)d_in[9];
    const float* wk = (const float*)d_in[10];
    const float* bk = (const float*)d_in[11];
    const float* wv = (const float*)d_in[12];
    const float* bv = (const float*)d_in[13];
    const float* wfc = (const float*)d_in[14];
    const float* bfc = (const float*)d_in[15];
    const float* lng = (const float*)d_in[16];
    const float* lnb = (const float*)d_in[17];
    const float* Wd = (const float*)d_in[18];
    const float* bd = (const float*)d_in[19];
    float* out = (float*)d_out;

    float *xb, *hbuf, *cbuf, *hlbuf;
    cudaGetSymbolAddress((void**)&xb, g_xbuf);
    cudaGetSymbolAddress((void**)&hbuf, g_h);
    cudaGetSymbolAddress((void**)&cbuf, g_c);
    cudaGetSymbolAddress((void**)&hlbuf, g_hl);
    float* x0 = xb;
    float* x1 = xb + (size_t)T * B * NHID;

    k_embed<<<T * B, 256>>>(tokens, embW, x0);

    const size_t DECN = (size_t)T * B * NTOK;
    for (int l = 0; l < NLAYERS; ++l) {
        const float* xin = (l == 0) ? x0 : x1;
        float* xout = (l == 0) ? x1 : x0;
        k_copy4<<<64, 256>>>((const float4*)(h0 + (size_t)l * B * NHID), (float4*)hbuf);
        k_copy4<<<64, 256>>>((const float4*)(c0 + (size_t)l * B * NHID), (float4*)cbuf);
        const float* Wih_l = Wih + (size_t)l * NB * 4 * BS * NINP;
        const float* Whh_l = Whh + (size_t)l * NB * 4 * BS * BS;
        const float* bih_l = bih + (size_t)l * NB * 4 * BS;
        const float* bhh_l = bhh + (size_t)l * NB * 4 * BS;
        for (int t = 0; t < T; ++t) {
            k_gates<<<dim3(32, 4), 128>>>(xin + (size_t)t * B * NHID, Wih_l, Whh_l,
                                          bih_l, bhh_l, hbuf, cbuf, hlbuf);
            k_mha<<<dim3(4, 64), 256>>>(hlbuf, hbuf, wq, bq, wk, bk, wv, bv, wfc, bfc,
                                        lng, lnb, xout + (size_t)t * B * NHID);
        }
        k_copy4<<<64, 256>>>((const float4*)hbuf,
                             (float4*)(out + DECN + (size_t)l * B * NHID));
        k_copy4<<<64, 256>>>((const float4*)cbuf,
                             (float4*)(out + DECN + (size_t)NLAYERS * B * NHID +
                                       (size_t)l * B * NHID));
    }
    // final activations are in x0 (layer 1 wrote there)
    k_dec<<<dim3(32, 250), 256>>>(x0, Wd, bd, out);
}

// round 2
// speedup vs baseline: 1.3854x; 1.3854x over previous
#include <cuda_runtime.h>

#define NLAYERS 2
#define NB 4
#define BS 256
#define NHID 1024
#define NINP 1024
#define NTOK 32000
#define T 64
#define B 64
#define DK 16

// ---------------- scratch (device globals: no allocation allowed) ----------
__device__ float g_xbuf[2][(size_t)T * B * NHID];  // ping-pong layer activations
__device__ float g_xg[(size_t)T * B * NB * 4 * BS];  // precomputed x-gates [4096 x 4096]
__device__ float g_h[B * NHID];                    // current h state
__device__ float g_c[B * NHID];                    // current c state
__device__ float g_hl[B * NHID];                   // h_lstm (pre-MHA)

// ---------------- f32x2 helpers (sm_103a packed fp32 FMA) ------------------
__device__ __forceinline__ unsigned long long splat2(float a) {
    unsigned long long r;
    unsigned int u = __float_as_uint(a);
    asm("mov.b64 %0, {%1, %1};" : "=l"(r) : "r"(u));
    return r;
}
__device__ __forceinline__ unsigned long long pack2(float x, float y) {
    unsigned long long r;
    asm("mov.b64 %0, {%1, %2};" : "=l"(r)
        : "r"(__float_as_uint(x)), "r"(__float_as_uint(y)));
    return r;
}
__device__ __forceinline__ void ffma2(unsigned long long &c, unsigned long long a,
                                      unsigned long long b) {
    asm("fma.rn.f32x2 %0, %1, %2, %0;" : "+l"(c) : "l"(a), "l"(b));
}
__device__ __forceinline__ float2 unpk(unsigned long long v) {
    unsigned int x, y;
    asm("mov.b64 {%0, %1}, %2;" : "=r"(x), "=r"(y) : "l"(v));
    return make_float2(__uint_as_float(x), __uint_as_float(y));
}
__device__ __forceinline__ float sigmoidf_(float x) { return 1.f / (1.f + expf(-x)); }

// ---------------- embedding gather ------------------------------------------
__global__ void k_embed(const int* __restrict__ tokens, const float* __restrict__ embW,
                        float* __restrict__ x) {
    int tb = blockIdx.x;
    int tok = tokens[tb];
    const float4* src = (const float4*)(embW + (size_t)tok * NINP);
    float4* dst = (float4*)(x + (size_t)tb * NINP);
    dst[threadIdx.x] = src[threadIdx.x];
}

// ---------------- 64K-float copy (state init / writeout) --------------------
__global__ void k_copy4(const float4* __restrict__ s, float4* __restrict__ d) {
    int i = blockIdx.x * blockDim.x + threadIdx.x;
    d[i] = s[i];
}

// ---------------- generic 128x128 f32x2 GEMM: out = X @ W^T ------------------
// X: [M rows, K=1024], W: [N rows, K=1024]. Used for xg precompute (N=4096).
__global__ void __launch_bounds__(256, 2) k_gemm_xg(
    const float* __restrict__ X, const float* __restrict__ Wd,
    float* __restrict__ out) {
    __shared__ __align__(16) float sa[16][132];
    __shared__ __align__(16) float sb[16][132];
    const int m0 = blockIdx.x * 128;
    const int n0 = blockIdx.y * 128;
    const int tid = threadIdx.x;
    const int tn = tid & 15, tm = tid >> 4;
    unsigned long long acc[8][4];
#pragma unroll
    for (int i = 0; i < 8; i++)
#pragma unroll
        for (int p = 0; p < 4; p++) acc[i][p] = 0ULL;

    float4 pa[2], pb[2];
#pragma unroll
    for (int i = 0; i < 2; ++i) {
        int lid = tid + i * 256;
        int row = lid >> 2, kq = lid & 3;
        pa[i] = *(const float4*)(X + (size_t)(m0 + row) * NHID + kq * 4);
        pb[i] = *(const float4*)(Wd + (size_t)(n0 + row) * NHID + kq * 4);
    }
    for (int k0 = 0; k0 < NHID; k0 += 16) {
#pragma unroll
        for (int i = 0; i < 2; ++i) {
            int lid = tid + i * 256;
            int row = lid >> 2, kq = lid & 3;
            sa[kq * 4 + 0][row] = pa[i].x; sa[kq * 4 + 1][row] = pa[i].y;
            sa[kq * 4 + 2][row] = pa[i].z; sa[kq * 4 + 3][row] = pa[i].w;
            sb[kq * 4 + 0][row] = pb[i].x; sb[kq * 4 + 1][row] = pb[i].y;
            sb[kq * 4 + 2][row] = pb[i].z; sb[kq * 4 + 3][row] = pb[i].w;
        }
        __syncthreads();
        if (k0 + 16 < NHID) {
#pragma unroll
            for (int i = 0; i < 2; ++i) {
                int lid = tid + i * 256;
                int row = lid >> 2, kq = lid & 3;
                pa[i] = *(const float4*)(X + (size_t)(m0 + row) * NHID + (k0 + 16) + kq * 4);
                pb[i] = *(const float4*)(Wd + (size_t)(n0 + row) * NHID + (k0 + 16) + kq * 4);
            }
        }
#pragma unroll
        for (int k = 0; k < 16; ++k) {
            unsigned long long b2[4];
#pragma unroll
            for (int p = 0; p < 4; ++p)
                b2[p] = *(const unsigned long long*)&sb[k][p * 32 + tn * 2];
#pragma unroll
            for (int i = 0; i < 8; ++i) {
                unsigned long long as = splat2(sa[k][tm * 8 + i]);
#pragma unroll
                for (int p = 0; p < 4; ++p) ffma2(acc[i][p], as, b2[p]);
            }
        }
        __syncthreads();
    }
#pragma unroll
    for (int i = 0; i < 8; ++i) {
        int m = m0 + tm * 8 + i;
#pragma unroll
        for (int p = 0; p < 4; ++p) {
            int nn = n0 + p * 32 + tn * 2;
            float2 v = unpk(acc[i][p]);
            *(float2*)(out + (size_t)m * (NB * 4 * BS) + nn) = v;
        }
    }
}

// ---------------- recurrent gates (h-part only) + LSTM cell ------------------
// acc initialized from precomputed x-gates; K reduced to 256 (h @ Whh).
// grid: (BS/8=32, NB=4) = 128 CTAs, 128 threads.
__global__ void __launch_bounds__(128) k_gates_h(
    const float* __restrict__ xg_t,  // [B][4096], this timestep's x-gates
    const float* __restrict__ Whh,   // [NB][4BS][BS] (layer slice)
    const float* __restrict__ bih, const float* __restrict__ bhh,  // [NB][4BS]
    const float* __restrict__ hprev,                               // [B][NHID]
    float* __restrict__ c, float* __restrict__ hl) {
    __shared__ __align__(16) float sa[32][65];
    __shared__ __align__(16) float sw[32][34];
    const int n = blockIdx.y;
    const int j0 = blockIdx.x * 8;
    const int tid = threadIdx.x;
    const int tj = tid & 7, tb4 = tid >> 3;
    const int j = j0 + tj;

    // init accumulators from precomputed x @ Wih (+ both biases)
    unsigned long long acc[4][2];
    const float b_i = bih[n * 4 * BS + 0 * BS + j] + bhh[n * 4 * BS + 0 * BS + j];
    const float b_f = bih[n * 4 * BS + 1 * BS + j] + bhh[n * 4 * BS + 1 * BS + j];
    const float b_g = bih[n * 4 * BS + 2 * BS + j] + bhh[n * 4 * BS + 2 * BS + j];
    const float b_o = bih[n * 4 * BS + 3 * BS + j] + bhh[n * 4 * BS + 3 * BS + j];
#pragma unroll
    for (int bi = 0; bi < 4; ++bi) {
        int bb = tb4 * 4 + bi;
        const float* xr = xg_t + (size_t)bb * (NB * 4 * BS) + n * 4 * BS + j;
        acc[bi][0] = pack2(xr[0] + b_i, xr[BS] + b_f);
        acc[bi][1] = pack2(xr[2 * BS] + b_g, xr[3 * BS] + b_o);
    }

    const float* A = hprev + n * BS;
    const float* W = Whh + n * 4 * BS * BS;
    for (int k0 = 0; k0 < BS; k0 += 32) {
        __syncthreads();
#pragma unroll
        for (int i = 0; i < 4; ++i) {
            int lid = tid + i * 128;
            int bb = lid >> 3, kq = lid & 7;
            float4 v = *(const float4*)(A + (size_t)bb * NHID + k0 + kq * 4);
            sa[kq * 4 + 0][bb] = v.x; sa[kq * 4 + 1][bb] = v.y;
            sa[kq * 4 + 2][bb] = v.z; sa[kq * 4 + 3][bb] = v.w;
        }
#pragma unroll
        for (int i = 0; i < 2; ++i) {
            int lid = tid + i * 128;
            int col = lid >> 3, kq = lid & 7;
            int jj = col >> 2, g = col & 3;
            float4 v = *(const float4*)(W + (size_t)(g * BS + j0 + jj) * BS + k0 + kq * 4);
            sw[kq * 4 + 0][col] = v.x; sw[kq * 4 + 1][col] = v.y;
            sw[kq * 4 + 2][col] = v.z; sw[kq * 4 + 3][col] = v.w;
        }
        __syncthreads();
#pragma unroll
        for (int k = 0; k < 32; ++k) {
            unsigned long long w01 = *(const unsigned long long*)&sw[k][tj * 4];
            unsigned long long w23 = *(const unsigned long long*)&sw[k][tj * 4 + 2];
#pragma unroll
            for (int bi = 0; bi < 4; ++bi) {
                unsigned long long as = splat2(sa[k][tb4 * 4 + bi]);
                ffma2(acc[bi][0], as, w01);
                ffma2(acc[bi][1], as, w23);
            }
        }
    }
    // epilogue: LSTM cell (biases already folded into acc)
#pragma unroll
    for (int bi = 0; bi < 4; ++bi) {
        int bb = tb4 * 4 + bi;
        float2 g01 = unpk(acc[bi][0]);
        float2 g23 = unpk(acc[bi][1]);
        int idx = bb * NHID + n * BS + j;
        float cn = sigmoidf_(g01.y) * c[idx] + sigmoidf_(g01.x) * tanhf(g23.x);
        c[idx] = cn;
        hl[idx] = sigmoidf_(g23.y) * tanhf(cn);
    }
}

// ---------------- fused MHA + residual + LayerNorm ---------------------------
__global__ void __launch_bounds__(256) k_mha(
    const float* __restrict__ hl, float* __restrict__ h,
    const float* __restrict__ wq, const float* __restrict__ bq,
    const float* __restrict__ wk, const float* __restrict__ bk,
    const float* __restrict__ wv, const float* __restrict__ bv,
    const float* __restrict__ wfc, const float* __restrict__ bfc,
    const float* __restrict__ lng, const float* __restrict__ lnb,
    float* __restrict__ ys) {
    const int n = blockIdx.x, b = blockIdx.y;
    __shared__ float sh[NB][BS];
    __shared__ float sq[DK], sk[NB][DK], sv[NB][DK], ssc[NB], sp[NB], so[DK];
    __shared__ float sred[8];
    const int tid = threadIdx.x;
#pragma unroll
    for (int i = 0; i < 4; ++i) {
        int idx = tid + i * 256;
        sh[idx >> 8][idx & 255] = hl[b * NHID + idx];
    }
    __syncthreads();
    if (tid < 144) {
        const float *wp, *bp, *hv; float* dst; int d;
        if (tid < 16) { d = tid; wp = wq; bp = bq; hv = sh[n]; dst = &sq[d]; }
        else if (tid < 80) { int m = (tid - 16) >> 4; d = (tid - 16) & 15;
                             wp = wk; bp = bk; hv = sh[m]; dst = &sk[m][d]; }
        else { int m = (tid - 80) >> 4; d = (tid - 80) & 15;
               wp = wv; bp = bv; hv = sh[m]; dst = &sv[m][d]; }
        const float* w = wp + d * BS;
        float a0 = 0, a1 = 0, a2 = 0, a3 = 0;
#pragma unroll 8
        for (int jj = 0; jj < BS; jj += 4) {
            a0 += hv[jj] * w[jj];         a1 += hv[jj + 1] * w[jj + 1];
            a2 += hv[jj + 2] * w[jj + 2]; a3 += hv[jj + 3] * w[jj + 3];
        }
        *dst = a0 + a1 + a2 + a3 + bp[d];
    }
    __syncthreads();
    if (tid < 4) {
        float s = 0;
#pragma unroll
        for (int d = 0; d < DK; ++d) s += sq[d] * sk[tid][d];
        ssc[tid] = s * 0.25f;
    }
    __syncthreads();
    if (tid < 4) {
        float mx = fmaxf(fmaxf(ssc[0], ssc[1]), fmaxf(ssc[2], ssc[3]));
        float sum = expf(ssc[0] - mx) + expf(ssc[1] - mx) +
                    expf(ssc[2] - mx) + expf(ssc[3] - mx);
        sp[tid] = expf(ssc[tid] - mx) / sum;
    }
    __syncthreads();
    if (tid < DK) {
        float o = 0;
#pragma unroll
        for (int m = 0; m < NB; ++m) o += sp[m] * sv[m][tid];
        so[tid] = o;
    }
    __syncthreads();
    float val = bfc[tid] + sh[n][tid];
#pragma unroll
    for (int d = 0; d < DK; ++d) val += so[d] * wfc[tid * DK + d];
    float s = val;
#pragma unroll
    for (int off = 16; off; off >>= 1) s += __shfl_down_sync(0xffffffffu, s, off);
    if ((tid & 31) == 0) sred[tid >> 5] = s;
    __syncthreads();
    float mu = 0;
#pragma unroll
    for (int i = 0; i < 8; ++i) mu += sred[i];
    mu *= (1.f / BS);
    __syncthreads();
    float dv = val - mu;
    float s2 = dv * dv;
#pragma unroll
    for (int off = 16; off; off >>= 1) s2 += __shfl_down_sync(0xffffffffu, s2, off);
    if ((tid & 31) == 0) sred[tid >> 5] = s2;
    __syncthreads();
    float var = 0;
#pragma unroll
    for (int i = 0; i < 8; ++i) var += sred[i];
    var *= (1.f / BS);
    float y = dv * rsqrtf(var + 1e-5f) * lng[tid] + lnb[tid];
    int idx = b * NHID + n * BS + tid;
    h[idx] = y;
    ys[idx] = y;
}

// ---------------- decoder GEMM: [4096,1024] x [32000,1024]^T + bias ----------
__global__ void __launch_bounds__(256, 2) k_dec(
    const float* __restrict__ X, const float* __restrict__ Wd,
    const float* __restrict__ bias, float* __restrict__ out) {
    __shared__ __align__(16) float sa[16][132];
    __shared__ __align__(16) float sb[16][132];
    const int m0 = blockIdx.x * 128;
    const int n0 = blockIdx.y * 128;
    const int tid = threadIdx.x;
    const int tn = tid & 15, tm = tid >> 4;
    unsigned long long acc[8][4];
#pragma unroll
    for (int i = 0; i < 8; i++)
#pragma unroll
        for (int p = 0; p < 4; p++) acc[i][p] = 0ULL;

    float4 pa[2], pb[2];
#pragma unroll
    for (int i = 0; i < 2; ++i) {
        int lid = tid + i * 256;
        int row = lid >> 2, kq = lid & 3;
        pa[i] = *(const float4*)(X + (size_t)(m0 + row) * NHID + kq * 4);
        pb[i] = *(const float4*)(Wd + (size_t)(n0 + row) * NHID + kq * 4);
    }
    for (int k0 = 0; k0 < NHID; k0 += 16) {
#pragma unroll
        for (int i = 0; i < 2; ++i) {
            int lid = tid + i * 256;
            int row = lid >> 2, kq = lid & 3;
            sa[kq * 4 + 0][row] = pa[i].x; sa[kq * 4 + 1][row] = pa[i].y;
            sa[kq * 4 + 2][row] = pa[i].z; sa[kq * 4 + 3][row] = pa[i].w;
            sb[kq * 4 + 0][row] = pb[i].x; sb[kq * 4 + 1][row] = pb[i].y;
            sb[kq * 4 + 2][row] = pb[i].z; sb[kq * 4 + 3][row] = pb[i].w;
        }
        __syncthreads();
        if (k0 + 16 < NHID) {
#pragma unroll
            for (int i = 0; i < 2; ++i) {
                int lid = tid + i * 256;
                int row = lid >> 2, kq = lid & 3;
                pa[i] = *(const float4*)(X + (size_t)(m0 + row) * NHID + (k0 + 16) + kq * 4);
                pb[i] = *(const float4*)(Wd + (size_t)(n0 + row) * NHID + (k0 + 16) + kq * 4);
            }
        }
#pragma unroll
        for (int k = 0; k < 16; ++k) {
            unsigned long long b2[4];
#pragma unroll
            for (int p = 0; p < 4; ++p)
                b2[p] = *(const unsigned long long*)&sb[k][p * 32 + tn * 2];
#pragma unroll
            for (int i = 0; i < 8; ++i) {
                unsigned long long as = splat2(sa[k][tm * 8 + i]);
#pragma unroll
                for (int p = 0; p < 4; ++p) ffma2(acc[i][p], as, b2[p]);
            }
        }
        __syncthreads();
    }
#pragma unroll
    for (int i = 0; i < 8; ++i) {
        int m = m0 + tm * 8 + i;
#pragma unroll
        for (int p = 0; p < 4; ++p) {
            int nn = n0 + p * 32 + tn * 2;
            float2 v = unpk(acc[i][p]);
            float2 r = make_float2(v.x + bias[nn], v.y + bias[nn + 1]);
            *(float2*)(out + (size_t)m * NTOK + nn) = r;
        }
    }
}

// ---------------- host driver ------------------------------------------------
extern "C" void kernel_launch(void* const* d_in, const int* in_sizes, int n_in,
                              void* d_out, int out_size) {
    const int* tokens = (const int*)d_in[0];
    const float* h0 = (const float*)d_in[1];
    const float* c0 = (const float*)d_in[2];
    const float* embW = (const float*)d_in[3];
    const float* Wih = (const float*)d_in[4];
    const float* Whh = (const float*)d_in[5];
    const float* bih = (const float*)d_in[6];
    const float* bhh = (const float*)d_in[7];
    const float* wq = (const float*)d_in[8];
    const float* bq = (const float*)d_in[9];
    const float* wk = (const float*)d_in[10];
    const float* bk = (const float*)d_in[11];
    const float* wv = (const float*)d_in[12];
    const float* bv = (const float*)d_in[13];
    const float* wfc = (const float*)d_in[14];
    const float* bfc = (const float*)d_in[15];
    const float* lng = (const float*)d_in[16];
    const float* lnb = (const float*)d_in[17];
    const float* Wd = (const float*)d_in[18];
    const float* bd = (const float*)d_in[19];
    float* out = (float*)d_out;

    float *xb, *xg, *hbuf, *cbuf, *hlbuf;
    cudaGetSymbolAddress((void**)&xb, g_xbuf);
    cudaGetSymbolAddress((void**)&xg, g_xg);
    cudaGetSymbolAddress((void**)&hbuf, g_h);
    cudaGetSymbolAddress((void**)&cbuf, g_c);
    cudaGetSymbolAddress((void**)&hlbuf, g_hl);
    float* x0 = xb;
    float* x1 = xb + (size_t)T * B * NHID;

    k_embed<<<T * B, 256>>>(tokens, embW, x0);

    const size_t DECN = (size_t)T * B * NTOK;
    for (int l = 0; l < NLAYERS; ++l) {
        const float* xin = (l == 0) ? x0 : x1;
        float* xout = (l == 0) ? x1 : x0;
        k_copy4<<<64, 256>>>((const float4*)(h0 + (size_t)l * B * NHID), (float4*)hbuf);
        k_copy4<<<64, 256>>>((const float4*)(c0 + (size_t)l * B * NHID), (float4*)cbuf);
        const float* Wih_l = Wih + (size_t)l * NB * 4 * BS * NINP;
        const float* Whh_l = Whh + (size_t)l * NB * 4 * BS * BS;
        const float* bih_l = bih + (size_t)l * NB * 4 * BS;
        const float* bhh_l = bhh + (size_t)l * NB * 4 * BS;
        // hoisted input-gates GEMM: xg = xin @ Wih_l^T  [4096 x 4096]
        k_gemm_xg<<<dim3(32, 32), 256>>>(xin, Wih_l, xg);
        for (int t = 0; t < T; ++t) {
            k_gates_h<<<dim3(32, 4), 128>>>(xg + (size_t)t * B * (NB * 4 * BS), Whh_l,
                                            bih_l, bhh_l, hbuf, cbuf, hlbuf);
            k_mha<<<dim3(4, 64), 256>>>(hlbuf, hbuf, wq, bq, wk, bk, wv, bv, wfc, bfc,
                                        lng, lnb, xout + (size_t)t * B * NHID);
        }
        k_copy4<<<64, 256>>>((const float4*)hbuf,
                             (float4*)(out + DECN + (size_t)l * B * NHID));
        k_copy4<<<64, 256>>>((const float4*)cbuf,
                             (float4*)(out + DECN + (size_t)NLAYERS * B * NHID +
                                       (size_t)l * B * NHID));
    }
    k_dec<<<dim3(32, 250), 256>>>(x0, Wd, bd, out);
}

// round 5
// speedup vs baseline: 1.5708x; 1.1338x over previous
#include <cuda_runtime.h>
#include <cuda_bf16.h>
#include <cstdint>

#define NLAYERS 2
#define NB 4
#define BS 256
#define NHID 1024
#define NINP 1024
#define NTOK 32000
#define T 64
#define B 64
#define DK 16

// ---------------- scratch (device globals: no allocation allowed) ----------
__device__ float g_xbuf[2][(size_t)T * B * NHID];
__device__ float g_xg[(size_t)T * B * NB * 4 * BS];
__device__ float g_h[B * NHID];
__device__ float g_c[B * NHID];
__device__ float g_hl[B * NHID];

// ---------------- f32x2 helpers ---------------------------------------------
__device__ __forceinline__ unsigned long long splat2(float a) {
    unsigned long long r;
    unsigned int u = __float_as_uint(a);
    asm("mov.b64 %0, {%1, %1};" : "=l"(r) : "r"(u));
    return r;
}
__device__ __forceinline__ unsigned long long pack2(float x, float y) {
    unsigned long long r;
    asm("mov.b64 %0, {%1, %2};" : "=l"(r)
        : "r"(__float_as_uint(x)), "r"(__float_as_uint(y)));
    return r;
}
__device__ __forceinline__ void ffma2(unsigned long long &c, unsigned long long a,
                                      unsigned long long b) {
    asm("fma.rn.f32x2 %0, %1, %2, %0;" : "+l"(c) : "l"(a), "l"(b));
}
__device__ __forceinline__ float2 unpk(unsigned long long v) {
    unsigned int x, y;
    asm("mov.b64 {%0, %1}, %2;" : "=r"(x), "=r"(y) : "l"(v));
    return make_float2(__uint_as_float(x), __uint_as_float(y));
}
__device__ __forceinline__ float sigmoidf_(float x) { return 1.f / (1.f + expf(-x)); }

// ---------------- bf16 split helpers ----------------------------------------
__device__ __forceinline__ uint32_t pkbf(float a, float b) {
    __nv_bfloat162 t = __floats2bfloat162_rn(a, b);
    return *reinterpret_cast<uint32_t*>(&t);
}
__device__ __forceinline__ void cvt8(const float4 v0, const float4 v1,
                                     uint4 &hi, uint4 &lo) {
    float f[8] = {v0.x, v0.y, v0.z, v0.w, v1.x, v1.y, v1.z, v1.w};
    float h[8], l[8];
#pragma unroll
    for (int i = 0; i < 8; ++i) {
        h[i] = __bfloat162float(__float2bfloat16(f[i]));
        l[i] = f[i] - h[i];
    }
    hi.x = pkbf(h[0], h[1]); hi.y = pkbf(h[2], h[3]);
    hi.z = pkbf(h[4], h[5]); hi.w = pkbf(h[6], h[7]);
    lo.x = pkbf(l[0], l[1]); lo.y = pkbf(l[2], l[3]);
    lo.z = pkbf(l[4], l[5]); lo.w = pkbf(l[6], l[7]);
}

// ---------------- HMMA (mma.sync) 16x8x16 bf16 -------------------------------
__device__ __forceinline__ void mma16816(float* d, uint32_t a0, uint32_t a1,
                                         uint32_t a2, uint32_t a3,
                                         uint32_t b0, uint32_t b1) {
    asm volatile(
        "mma.sync.aligned.m16n8k16.row.col.f32.bf16.bf16.f32 "
        "{%0,%1,%2,%3},{%4,%5,%6,%7},{%8,%9},{%0,%1,%2,%3};"
        : "+f"(d[0]), "+f"(d[1]), "+f"(d[2]), "+f"(d[3])
        : "r"(a0), "r"(a1), "r"(a2), "r"(a3), "r"(b0), "r"(b1));
}

// ---------------- decoder GEMM via mma.sync (3-term bf16 compensation) -------
// out = X @ W^T + bias.  CTA 128x128, 8 warps (64x32 warp tile), K-chunk 32.
__global__ void __launch_bounds__(256, 1) k_mma(
    const float* __restrict__ X, const float* __restrict__ W,
    const float* __restrict__ bias, float* __restrict__ out, int ldc) {
    __shared__ __align__(16) char sm[40960];
    const int tid = threadIdx.x;
    const int wid = tid >> 5, lid = tid & 31;
    const int m0 = blockIdx.x * 128;
    const int n0 = blockIdx.y * 128;
    const int warpM = wid >> 2;
    const int warpN = wid & 3;
    const int laneR = lid >> 2;
    const int laneC2 = (lid & 3) * 2;

    const int lrow = tid >> 1;
    const int lseg = tid & 1;
    const float* arow = X + (size_t)(m0 + lrow) * 1024 + lseg * 16;
    const float* brow = W + (size_t)(n0 + lrow) * 1024 + lseg * 16;
    const int sst = lrow * 80 + lseg * 32;

    float acc[4][4][4];
#pragma unroll
    for (int a = 0; a < 4; ++a)
#pragma unroll
        for (int b = 0; b < 4; ++b)
#pragma unroll
            for (int c = 0; c < 4; ++c) acc[a][b][c] = 0.f;

    float4 ra[4], rb[4];
#pragma unroll
    for (int i = 0; i < 4; ++i) {
        ra[i] = *(const float4*)(arow + i * 4);
        rb[i] = *(const float4*)(brow + i * 4);
    }

    const int NCH = 1024 / 32;
    for (int kc = 0; kc < NCH; ++kc) {
        {
            uint4 h0, l0, h1, l1;
            cvt8(ra[0], ra[1], h0, l0);
            cvt8(ra[2], ra[3], h1, l1);
            *(uint4*)(sm + sst) = h0;
            *(uint4*)(sm + sst + 16) = h1;
            *(uint4*)(sm + 10240 + sst) = l0;
            *(uint4*)(sm + 10240 + sst + 16) = l1;
            cvt8(rb[0], rb[1], h0, l0);
            cvt8(rb[2], rb[3], h1, l1);
            *(uint4*)(sm + 20480 + sst) = h0;
            *(uint4*)(sm + 20480 + sst + 16) = h1;
            *(uint4*)(sm + 30720 + sst) = l0;
            *(uint4*)(sm + 30720 + sst + 16) = l1;
        }
        __syncthreads();
        if (kc + 1 < NCH) {
            const float* an = arow + (kc + 1) * 32;
            const float* bn = brow + (kc + 1) * 32;
#pragma unroll
            for (int i = 0; i < 4; ++i) {
                ra[i] = *(const float4*)(an + i * 4);
                rb[i] = *(const float4*)(bn + i * 4);
            }
        }
#pragma unroll
        for (int ks = 0; ks < 2; ++ks) {
            uint32_t ah[4][4], al[4][4], bh[4][2], bl[4][2];
#pragma unroll
            for (int mt = 0; mt < 4; ++mt) {
                int hb = (warpM * 64 + mt * 16 + laneR) * 40 + ks * 16 + laneC2;
                const char* pA = sm + hb * 2;
#pragma unroll
                for (int q = 0; q < 4; ++q) {
                    int off = ((q & 1) ? 8 * 80 : 0) + ((q & 2) ? 16 : 0);
                    ah[mt][q] = *(const uint32_t*)(pA + off);
                    al[mt][q] = *(const uint32_t*)(pA + 10240 + off);
                }
            }
#pragma unroll
            for (int nt = 0; nt < 4; ++nt) {
                int hb = (warpN * 32 + nt * 8 + laneR) * 40 + ks * 16 + laneC2;
                const char* pB = sm + 20480 + hb * 2;
                bh[nt][0] = *(const uint32_t*)(pB);
                bh[nt][1] = *(const uint32_t*)(pB + 16);
                bl[nt][0] = *(const uint32_t*)(pB + 10240);
                bl[nt][1] = *(const uint32_t*)(pB + 10240 + 16);
            }
#pragma unroll
            for (int mt = 0; mt < 4; ++mt)
#pragma unroll
                for (int nt = 0; nt < 4; ++nt)
                    mma16816(acc[mt][nt], ah[mt][0], ah[mt][1], ah[mt][2], ah[mt][3],
                             bh[nt][0], bh[nt][1]);
#pragma unroll
            for (int mt = 0; mt < 4; ++mt)
#pragma unroll
                for (int nt = 0; nt < 4; ++nt)
                    mma16816(acc[mt][nt], ah[mt][0], ah[mt][1], ah[mt][2], ah[mt][3],
                             bl[nt][0], bl[nt][1]);
#pragma unroll
            for (int mt = 0; mt < 4; ++mt)
#pragma unroll
                for (int nt = 0; nt < 4; ++nt)
                    mma16816(acc[mt][nt], al[mt][0], al[mt][1], al[mt][2], al[mt][3],
                             bh[nt][0], bh[nt][1]);
        }
        __syncthreads();
    }

#pragma unroll
    for (int mt = 0; mt < 4; ++mt) {
        int m = m0 + warpM * 64 + mt * 16 + laneR;
#pragma unroll
        for (int nt = 0; nt < 4; ++nt) {
            int n = n0 + warpN * 32 + nt * 8 + laneC2;
            float bx = bias[n], by = bias[n + 1];
            *(float2*)(out + (size_t)m * ldc + n) =
                make_float2(acc[mt][nt][0] + bx, acc[mt][nt][1] + by);
            *(float2*)(out + (size_t)(m + 8) * ldc + n) =
                make_float2(acc[mt][nt][2] + bx, acc[mt][nt][3] + by);
        }
    }
}

// ---------------- xg precompute GEMM (exact fp32, f32x2) ---------------------
// out[m][n] = sum_k X[m][k] * W[n][k];  M=4096, N=4096, K=1024.
__global__ void __launch_bounds__(256, 2) k_gemm_xg(
    const float* __restrict__ X, const float* __restrict__ Wd,
    float* __restrict__ out) {
    __shared__ __align__(16) float sa[16][132];
    __shared__ __align__(16) float sb[16][132];
    const int m0 = blockIdx.x * 128;
    const int n0 = blockIdx.y * 128;
    const int tid = threadIdx.x;
    const int tn = tid & 15, tm = tid >> 4;
    unsigned long long acc[8][4];
#pragma unroll
    for (int i = 0; i < 8; i++)
#pragma unroll
        for (int p = 0; p < 4; p++) acc[i][p] = 0ULL;

    float4 pa[2], pb[2];
#pragma unroll
    for (int i = 0; i < 2; ++i) {
        int lid = tid + i * 256;
        int row = lid >> 2, kq = lid & 3;
        pa[i] = *(const float4*)(X + (size_t)(m0 + row) * NHID + kq * 4);
        pb[i] = *(const float4*)(Wd + (size_t)(n0 + row) * NHID + kq * 4);
    }
    for (int k0 = 0; k0 < NHID; k0 += 16) {
#pragma unroll
        for (int i = 0; i < 2; ++i) {
            int lid = tid + i * 256;
            int row = lid >> 2, kq = lid & 3;
            sa[kq * 4 + 0][row] = pa[i].x; sa[kq * 4 + 1][row] = pa[i].y;
            sa[kq * 4 + 2][row] = pa[i].z; sa[kq * 4 + 3][row] = pa[i].w;
            sb[kq * 4 + 0][row] = pb[i].x; sb[kq * 4 + 1][row] = pb[i].y;
            sb[kq * 4 + 2][row] = pb[i].z; sb[kq * 4 + 3][row] = pb[i].w;
        }
        __syncthreads();
        if (k0 + 16 < NHID) {
#pragma unroll
            for (int i = 0; i < 2; ++i) {
                int lid = tid + i * 256;
                int row = lid >> 2, kq = lid & 3;
                pa[i] = *(const float4*)(X + (size_t)(m0 + row) * NHID + (k0 + 16) + kq * 4);
                pb[i] = *(const float4*)(Wd + (size_t)(n0 + row) * NHID + (k0 + 16) + kq * 4);
            }
        }
#pragma unroll
        for (int k = 0; k < 16; ++k) {
            unsigned long long b2[4];
#pragma unroll
            for (int p = 0; p < 4; ++p)
                b2[p] = *(const unsigned long long*)&sb[k][p * 32 + tn * 2];
#pragma unroll
            for (int i = 0; i < 8; ++i) {
                unsigned long long as = splat2(sa[k][tm * 8 + i]);
#pragma unroll
                for (int p = 0; p < 4; ++p) ffma2(acc[i][p], as, b2[p]);
            }
        }
        __syncthreads();
    }
#pragma unroll
    for (int i = 0; i < 8; ++i) {
        int m = m0 + tm * 8 + i;
#pragma unroll
        for (int p = 0; p < 4; ++p) {
            int nn = n0 + p * 32 + tn * 2;
            float2 v = unpk(acc[i][p]);
            *(float2*)(out + (size_t)m * (NB * 4 * BS) + nn) = v;
        }
    }
}

// ---------------- embedding gather ------------------------------------------
__global__ void k_embed(const int* __restrict__ tokens, const float* __restrict__ embW,
                        float* __restrict__ x) {
    int tb = blockIdx.x;
    int tok = tokens[tb];
    const float4* src = (const float4*)(embW + (size_t)tok * NINP);
    float4* dst = (float4*)(x + (size_t)tb * NINP);
    dst[threadIdx.x] = src[threadIdx.x];
}

__global__ void k_copy4(const float4* __restrict__ s, float4* __restrict__ d) {
    int i = blockIdx.x * blockDim.x + threadIdx.x;
    d[i] = s[i];
}

// ---------------- recurrent gates (h-part) + LSTM cell -----------------------
__global__ void __launch_bounds__(256) k_gates_h(
    const float* __restrict__ xg_t, const float* __restrict__ Whh,
    const float* __restrict__ bih, const float* __restrict__ bhh,
    const float* __restrict__ hprev,
    float* __restrict__ c, float* __restrict__ hl) {
    __shared__ __align__(16) float sa[32][65];
    __shared__ __align__(16) float sw[32][34];
    const int n = blockIdx.y;
    const int j0 = blockIdx.x * 8;
    const int tid = threadIdx.x;
    const int tj = tid & 7, tb2 = tid >> 3;
    const int j = j0 + tj;

    unsigned long long acc[2][2];
    const float b_i = bih[n * 4 * BS + 0 * BS + j] + bhh[n * 4 * BS + 0 * BS + j];
    const float b_f = bih[n * 4 * BS + 1 * BS + j] + bhh[n * 4 * BS + 1 * BS + j];
    const float b_g = bih[n * 4 * BS + 2 * BS + j] + bhh[n * 4 * BS + 2 * BS + j];
    const float b_o = bih[n * 4 * BS + 3 * BS + j] + bhh[n * 4 * BS + 3 * BS + j];
#pragma unroll
    for (int bi = 0; bi < 2; ++bi) {
        int bb = tb2 * 2 + bi;
        const float* xr = xg_t + (size_t)bb * (NB * 4 * BS) + n * 4 * BS + j;
        acc[bi][0] = pack2(xr[0] + b_i, xr[BS] + b_f);
        acc[bi][1] = pack2(xr[2 * BS] + b_g, xr[3 * BS] + b_o);
    }

    const float* A = hprev + n * BS;
    const float* W = Whh + n * 4 * BS * BS;
    for (int k0 = 0; k0 < BS; k0 += 32) {
        __syncthreads();
#pragma unroll
        for (int i = 0; i < 2; ++i) {
            int lid = tid + i * 256;
            int bb = lid >> 3, kq = lid & 7;
            float4 v = *(const float4*)(A + (size_t)bb * NHID + k0 + kq * 4);
            sa[kq * 4 + 0][bb] = v.x; sa[kq * 4 + 1][bb] = v.y;
            sa[kq * 4 + 2][bb] = v.z; sa[kq * 4 + 3][bb] = v.w;
        }
        {
            int col = tid >> 3, kq = tid & 7;
            int jj = col >> 2, g = col & 3;
            float4 v = *(const float4*)(W + (size_t)(g * BS + j0 + jj) * BS + k0 + kq * 4);
            sw[kq * 4 + 0][col] = v.x; sw[kq * 4 + 1][col] = v.y;
            sw[kq * 4 + 2][col] = v.z; sw[kq * 4 + 3][col] = v.w;
        }
        __syncthreads();
#pragma unroll
        for (int k = 0; k < 32; ++k) {
            unsigned long long w01 = *(const unsigned long long*)&sw[k][tj * 4];
            unsigned long long w23 = *(const unsigned long long*)&sw[k][tj * 4 + 2];
#pragma unroll
            for (int bi = 0; bi < 2; ++bi) {
                unsigned long long as = splat2(sa[k][tb2 * 2 + bi]);
                ffma2(acc[bi][0], as, w01);
                ffma2(acc[bi][1], as, w23);
            }
        }
    }
#pragma unroll
    for (int bi = 0; bi < 2; ++bi) {
        int bb = tb2 * 2 + bi;
        float2 g01 = unpk(acc[bi][0]);
        float2 g23 = unpk(acc[bi][1]);
        int idx = bb * NHID + n * BS + j;
        float cn = sigmoidf_(g01.y) * c[idx] + sigmoidf_(g01.x) * tanhf(g23.x);
        c[idx] = cn;
        hl[idx] = sigmoidf_(g23.y) * tanhf(cn);
    }
}

// ---------------- fused MHA + residual + LayerNorm ---------------------------
__global__ void __launch_bounds__(256) k_mha(
    const float* __restrict__ hl, float* __restrict__ h,
    const float* __restrict__ wq, const float* __restrict__ bq,
    const float* __restrict__ wk, const float* __restrict__ bk,
    const float* __restrict__ wv, const float* __restrict__ bv,
    const float* __restrict__ wfc, const float* __restrict__ bfc,
    const float* __restrict__ lng, const float* __restrict__ lnb,
    float* __restrict__ ys) {
    const int n = blockIdx.x, b = blockIdx.y;
    __shared__ float sh[NB][BS];
    __shared__ float sq[DK], sk[NB][DK], sv[NB][DK], ssc[NB], sp[NB], so[DK];
    __shared__ float sred[8];
    const int tid = threadIdx.x;
#pragma unroll
    for (int i = 0; i < 4; ++i) {
        int idx = tid + i * 256;
        sh[idx >> 8][idx & 255] = hl[b * NHID + idx];
    }
    __syncthreads();
    if (tid < 144) {
        const float *wp, *bp, *hv; float* dst; int d;
        if (tid < 16) { d = tid; wp = wq; bp = bq; hv = sh[n]; dst = &sq[d]; }
        else if (tid < 80) { int m = (tid - 16) >> 4; d = (tid - 16) & 15;
                             wp = wk; bp = bk; hv = sh[m]; dst = &sk[m][d]; }
        else { int m = (tid - 80) >> 4; d = (tid - 80) & 15;
               wp = wv; bp = bv; hv = sh[m]; dst = &sv[m][d]; }
        const float* w = wp + d * BS;
        float a0 = 0, a1 = 0, a2 = 0, a3 = 0;
#pragma unroll 8
        for (int jj = 0; jj < BS; jj += 4) {
            a0 += hv[jj] * w[jj];         a1 += hv[jj + 1] * w[jj + 1];
            a2 += hv[jj + 2] * w[jj + 2]; a3 += hv[jj + 3] * w[jj + 3];
        }
        *dst = a0 + a1 + a2 + a3 + bp[d];
    }
    __syncthreads();
    if (tid < 4) {
        float s = 0;
#pragma unroll
        for (int d = 0; d < DK; ++d) s += sq[d] * sk[tid][d];
        ssc[tid] = s * 0.25f;
    }
    __syncthreads();
    if (tid < 4) {
        float mx = fmaxf(fmaxf(ssc[0], ssc[1]), fmaxf(ssc[2], ssc[3]));
        float sum = expf(ssc[0] - mx) + expf(ssc[1] - mx) +
                    expf(ssc[2] - mx) + expf(ssc[3] - mx);
        sp[tid] = expf(ssc[tid] - mx) / sum;
    }
    __syncthreads();
    if (tid < DK) {
        float o = 0;
#pragma unroll
        for (int m = 0; m < NB; ++m) o += sp[m] * sv[m][tid];
        so[tid] = o;
    }
    __syncthreads();
    float val = bfc[tid] + sh[n][tid];
#pragma unroll
    for (int d = 0; d < DK; ++d) val += so[d] * wfc[tid * DK + d];
    float s = val;
#pragma unroll
    for (int off = 16; off; off >>= 1) s += __shfl_down_sync(0xffffffffu, s, off);
    if ((tid & 31) == 0) sred[tid >> 5] = s;
    __syncthreads();
    float mu = 0;
#pragma unroll
    for (int i = 0; i < 8; ++i) mu += sred[i];
    mu *= (1.f / BS);
    __syncthreads();
    float dv = val - mu;
    float s2 = dv * dv;
#pragma unroll
    for (int off = 16; off; off >>= 1) s2 += __shfl_down_sync(0xffffffffu, s2, off);
    if ((tid & 31) == 0) sred[tid >> 5] = s2;
    __syncthreads();
    float var = 0;
#pragma unroll
    for (int i = 0; i < 8; ++i) var += sred[i];
    var *= (1.f / BS);
    float y = dv * rsqrtf(var + 1e-5f) * lng[tid] + lnb[tid];
    int idx = b * NHID + n * BS + tid;
    h[idx] = y;
    ys[idx] = y;
}

// ---------------- host driver ------------------------------------------------
extern "C" void kernel_launch(void* const* d_in, const int* in_sizes, int n_in,
                              void* d_out, int out_size) {
    const int* tokens = (const int*)d_in[0];
    const float* h0 = (const float*)d_in[1];
    const float* c0 = (const float*)d_in[2];
    const float* embW = (const float*)d_in[3];
    const float* Wih = (const float*)d_in[4];
    const float* Whh = (const float*)d_in[5];
    const float* bih = (const float*)d_in[6];
    const float* bhh = (const float*)d_in[7];
    const float* wq = (const float*)d_in[8];
    const float* bq = (const float*)d_in[9];
    const float* wk = (const float*)d_in[10];
    const float* bk = (const float*)d_in[11];
    const float* wv = (const float*)d_in[12];
    const float* bv = (const float*)d_in[13];
    const float* wfc = (const float*)d_in[14];
    const float* bfc = (const float*)d_in[15];
    const float* lng = (const float*)d_in[16];
    const float* lnb = (const float*)d_in[17];
    const float* Wd = (const float*)d_in[18];
    const float* bd = (const float*)d_in[19];
    float* out = (float*)d_out;

    float *xb, *xg, *hbuf, *cbuf, *hlbuf;
    cudaGetSymbolAddress((void**)&xb, g_xbuf);
    cudaGetSymbolAddress((void**)&xg, g_xg);
    cudaGetSymbolAddress((void**)&hbuf, g_h);
    cudaGetSymbolAddress((void**)&cbuf, g_c);
    cudaGetSymbolAddress((void**)&hlbuf, g_hl);
    float* x0 = xb;
    float* x1 = xb + (size_t)T * B * NHID;

    k_embed<<<T * B, 256>>>(tokens, embW, x0);

    const size_t DECN = (size_t)T * B * NTOK;
    for (int l = 0; l < NLAYERS; ++l) {
        const float* xin = (l == 0) ? x0 : x1;
        float* xout = (l == 0) ? x1 : x0;
        k_copy4<<<64, 256>>>((const float4*)(h0 + (size_t)l * B * NHID), (float4*)hbuf);
        k_copy4<<<64, 256>>>((const float4*)(c0 + (size_t)l * B * NHID), (float4*)cbuf);
        const float* Wih_l = Wih + (size_t)l * NB * 4 * BS * NINP;
        const float* Whh_l = Whh + (size_t)l * NB * 4 * BS * BS;
        const float* bih_l = bih + (size_t)l * NB * 4 * BS;
        const float* bhh_l = bhh + (size_t)l * NB * 4 * BS;
        // hoisted input-gates GEMM (exact fp32): xg = xin @ Wih_l^T
        k_gemm_xg<<<dim3(32, 32), 256>>>(xin, Wih_l, xg);
        for (int t = 0; t < T; ++t) {
            k_gates_h<<<dim3(32, 4), 256>>>(xg + (size_t)t * B * (NB * 4 * BS), Whh_l,
                                            bih_l, bhh_l, hbuf, cbuf, hlbuf);
            k_mha<<<dim3(4, 64), 256>>>(hlbuf, hbuf, wq, bq, wk, bk, wv, bv, wfc, bfc,
                                        lng, lnb, xout + (size_t)t * B * NHID);
        }
        k_copy4<<<64, 256>>>((const float4*)hbuf,
                             (float4*)(out + DECN + (size_t)l * B * NHID));
        k_copy4<<<64, 256>>>((const float4*)cbuf,
                             (float4*)(out + DECN + (size_t)NLAYERS * B * NHID +
                                       (size_t)l * B * NHID));
    }
    // decoder on tensor cores (3-term bf16): out = x0 @ Wd^T + bd
    k_mma<<<dim3(32, 250), 256>>>(x0, Wd, bd, out, NTOK);
}